// round 17
// baseline (speedup 1.0000x reference)
#include <cuda_runtime.h>
#include <cuda_bf16.h>
#include <mma.h>
#include <math.h>

using namespace nvcuda;

#define CLOUDS 64
#define PPC    128
#define DIM    128
#define NNODES (CLOUDS * PPC)
#define EPSV   1e-5f

typedef unsigned long long ull;

// ---------------- scratch ------------------------------------------------------
__device__ float g_Y[NNODES * DIM];     // X @ W1
__device__ float g_ps[128 * 128];
__device__ float g_pss[128 * 128];
__device__ float g_bstats[256];         // [0:128) scale, [128:256) shift
__device__ unsigned g_cnt;              // arrival ticket
__device__ unsigned g_cnt2;             // exit ticket (reset)
__device__ unsigned g_flag;             // bstats-ready flag

// ---------------- helpers ------------------------------------------------------
__device__ __forceinline__ ull pack2(float lo, float hi) {
    ull r; asm("mov.b64 %0, {%1, %2};" : "=l"(r) : "f"(lo), "f"(hi)); return r;
}
__device__ __forceinline__ void unpack2(ull v, float& lo, float& hi) {
    asm("mov.b64 {%0, %1}, %2;" : "=f"(lo), "=f"(hi) : "l"(v));
}
__device__ __forceinline__ ull fma2(ull a, ull b, ull c) {
    ull d; asm("fma.rn.f32x2 %0, %1, %2, %3;" : "=l"(d) : "l"(a), "l"(b), "l"(c)); return d;
}
__device__ __forceinline__ ull add2(ull a, ull b) {
    ull d; asm("add.rn.f32x2 %0, %1, %2;" : "=l"(d) : "l"(a), "l"(b)); return d;
}
__device__ __forceinline__ float rsqrt_ap(float x) {
    float r; asm("rsqrt.approx.f32 %0, %1;" : "=f"(r) : "f"(x)); return r;
}
__device__ __forceinline__ float ex2_ap(float x) {
    float r; asm("ex2.approx.f32 %0, %1;" : "=f"(r) : "f"(x)); return r;
}

#define NEG1_2 0xBF800000BF800000ULL
#define LOG2E  1.4426950408889634f

// ============================================================================
// K0: Y = X @ W1 on tensor cores (split-bf16, 3 terms) — unchanged from R15.
// ============================================================================
#define LDB 136

__global__ void __launch_bounds__(256, 1)
k0_gemm(const float* __restrict__ X, const float* __restrict__ W1) {
    extern __shared__ __nv_bfloat16 smb[];
    __nv_bfloat16* Whi = smb;                       // [128][136]
    __nv_bfloat16* Wlo = smb + 128 * LDB;           // [128][136]
    __nv_bfloat16* Xhi = smb + 2 * 128 * LDB;       // [64][136]
    __nv_bfloat16* Xlo = Xhi + 64 * LDB;            // [64][136]

    const int tid = threadIdx.x;
    const int r0  = blockIdx.x * 64;

    #pragma unroll
    for (int t = 0; t < 64; t++) {
        int idx = tid + t * 256;
        int r = idx >> 7, c = idx & 127;
        float v = W1[idx];
        __nv_bfloat16 h = __float2bfloat16(v);
        Whi[r * LDB + c] = h;
        Wlo[r * LDB + c] = __float2bfloat16(v - __bfloat162float(h));
    }
    #pragma unroll
    for (int t = 0; t < 32; t++) {
        int idx = tid + t * 256;
        int r = idx >> 7, c = idx & 127;
        float v = X[(r0 + r) * DIM + c];
        __nv_bfloat16 h = __float2bfloat16(v);
        Xhi[r * LDB + c] = h;
        Xlo[r * LDB + c] = __float2bfloat16(v - __bfloat162float(h));
    }
    __syncthreads();

    const int wid = tid >> 5;
    const int rw  = wid >> 1;
    const int cw  = wid & 1;

    wmma::fragment<wmma::accumulator, 16, 16, 16, float> acc[4];
    #pragma unroll
    for (int c = 0; c < 4; c++) wmma::fill_fragment(acc[c], 0.f);

    #pragma unroll
    for (int ks = 0; ks < 8; ks++) {
        wmma::fragment<wmma::matrix_a, 16, 16, 16, __nv_bfloat16, wmma::row_major> ahi, alo;
        wmma::load_matrix_sync(ahi, Xhi + rw * 16 * LDB + ks * 16, LDB);
        wmma::load_matrix_sync(alo, Xlo + rw * 16 * LDB + ks * 16, LDB);
        #pragma unroll
        for (int c = 0; c < 4; c++) {
            wmma::fragment<wmma::matrix_b, 16, 16, 16, __nv_bfloat16, wmma::row_major> bhi, blo;
            int col = cw * 64 + c * 16;
            wmma::load_matrix_sync(bhi, Whi + ks * 16 * LDB + col, LDB);
            wmma::load_matrix_sync(blo, Wlo + ks * 16 * LDB + col, LDB);
            wmma::mma_sync(acc[c], ahi, bhi, acc[c]);
            wmma::mma_sync(acc[c], ahi, blo, acc[c]);
            wmma::mma_sync(acc[c], alo, bhi, acc[c]);
        }
    }

    #pragma unroll
    for (int c = 0; c < 4; c++) {
        wmma::store_matrix_sync(g_Y + (ull)(r0 + rw * 16) * DIM + cw * 64 + c * 16,
                                acc[c], DIM, wmma::mem_row_major);
    }
}

// ============================================================================
// KFUSED v2: branches 1+2 merged, TRANSPOSED warp mapping.
// 128 CTAs x 512 threads = 16 warps: warp = (i-half 0/1) x (d-window 0..7).
// lane = i within half (32 i's), thread covers 16 d.
// Per warp per j: w = distinct coalesced 128B LDS (1 wf);
// y_j / z_j 64B windows = broadcast loads.  No (w,w) duplication table.
// BN stats via resident-grid ticket + spin.  smem 163.5 KB.
// ============================================================================
#define SMF_FLOATS 41856

__global__ void __launch_bounds__(512, 1)
kfused(const float* __restrict__ X, const float* __restrict__ XYZ,
       const float* __restrict__ Wxyz, const float* __restrict__ bn_g,
       const float* __restrict__ bn_b, const float* __restrict__ b1,
       const float* __restrict__ ln_g, const float* __restrict__ ln_b,
       float* __restrict__ out) {
    extern __shared__ float sm[];
    float* ys   = sm;                    // [128][128]  (64 KB)
    float* zs   = sm + 16384;            // [128][128]  (64 KB) -> p2 stage after loop
    float* ws   = sm + 32768;            // [128 j][64 i] (32 KB) -> LN red / bstats stage
    float* xyzs = sm + 40960;            // [128][4]
    float* wxs  = sm + 41472;            // [3][128]

    const int tid  = threadIdx.x;
    const int w    = tid >> 5;           // 0..15
    const int lane = tid & 31;
    const int dwin = w & 7;              // d-window
    const int ih   = w >> 3;             // i-half
    const int i_l  = (ih << 5) | lane;   // 0..63
    const int dbase = dwin << 4;         // 0..112 step 16

    const int cta   = blockIdx.x;
    const int node0 = (cta >> 1) << 7;
    const int i0    = (cta & 1) << 6;

    // ---- stage Y, xyz, Wxyz ----
    {
        const float4* Yv = (const float4*)(g_Y + node0 * DIM);
        float4* ysv = (float4*)ys;
        #pragma unroll
        for (int t = 0; t < 8; t++) ysv[tid + t * 512] = Yv[tid + t * 512];
    }
    if (tid < 128) {
        const float* p = XYZ + (node0 + tid) * 3;
        xyzs[tid * 4 + 0] = p[0];
        xyzs[tid * 4 + 1] = p[1];
        xyzs[tid * 4 + 2] = p[2];
        xyzs[tid * 4 + 3] = 0.f;
    } else if (tid >= 128 && tid < 512) {
        if (tid - 128 < 384) wxs[tid - 128] = Wxyz[tid - 128];
    }
    __syncthreads();

    // ---- zs (full cloud) and ws (this CTA's 64 i, plain floats) ----
    #pragma unroll
    for (int t = 0; t < 32; t++) {
        int idx = tid + t * 512;
        int jn = idx >> 7;
        int d  = idx & 127;
        zs[idx] = xyzs[(jn << 2) + 0] * wxs[d]
                + xyzs[(jn << 2) + 1] * wxs[128 + d]
                + xyzs[(jn << 2) + 2] * wxs[256 + d];
    }
    #pragma unroll
    for (int t = 0; t < 16; t++) {
        int idx = tid + t * 512;      // 0..8191
        int ii = idx & 63;
        int jj = idx >> 6;
        float dx = xyzs[((i0 + ii) << 2) + 0] - xyzs[(jj << 2) + 0];
        float dy = xyzs[((i0 + ii) << 2) + 1] - xyzs[(jj << 2) + 1];
        float dz = xyzs[((i0 + ii) << 2) + 2] - xyzs[(jj << 2) + 2];
        float d2 = dx * dx + dy * dy + dz * dz;
        float dist = d2 * rsqrt_ap(fmaxf(d2, 1e-30f));
        ws[(jj << 6) + ii] = ex2_ap(-dist * LOG2E);   // diag -> 1 (finite)
    }

    ull b1p[8];
    {
        const ull* b1u = (const ull*)b1;
        int boff = dbase >> 1;
        #pragma unroll
        for (int p = 0; p < 8; p++) b1p[p] = b1u[boff + p];
    }
    __syncthreads();

    ull yi[8], zi[8];
    {
        const ull* ysu = (const ull*)ys;
        const ull* zsu = (const ull*)zs;
        int off = (((i0 + i_l) << 7) + dbase) >> 1;
        #pragma unroll
        for (int p = 0; p < 8; p++) { yi[p] = ysu[off + p]; zi[p] = zsu[off + p]; }
    }
    ull a1[8], a2[8];
    #pragma unroll
    for (int p = 0; p < 8; p++) { a1[p] = 0ULL; a2[p] = 0ULL; }

    // ---- fused main loop over j ----
    #pragma unroll 2
    for (int j = 0; j < 128; j++) {
        float wv = ws[(j << 6) + i_l];        // distinct coalesced per lane
        ull w2 = pack2(wv, wv);
        const ulonglong2* yj2 = (const ulonglong2*)(ys + (j << 7) + dbase);
        const ulonglong2* zj2 = (const ulonglong2*)(zs + (j << 7) + dbase);
        ulonglong2 ya = yj2[0], yb = yj2[1], yc = yj2[2], yd = yj2[3];
        ulonglong2 za = zj2[0], zb = zj2[1], zc = zj2[2], zd = zj2[3];
        ull yjp[8] = {ya.x, ya.y, yb.x, yb.y, yc.x, yc.y, yd.x, yd.y};
        ull zjp[8] = {za.x, za.y, zb.x, zb.y, zc.x, zc.y, zd.x, zd.y};
        #pragma unroll
        for (int p = 0; p < 8; p++) {
            float lo, hi;
            ull df = fma2(yjp[p], NEG1_2, yi[p]);   // y_i - y_j
            ull t  = fma2(w2, df, b1p[p]);          // w*diff + b1
            unpack2(t, lo, hi);
            lo = fmaxf(lo, 0.f); hi = fmaxf(hi, 0.f);
            a1[p] = add2(a1[p], pack2(lo, hi));

            ull dz = fma2(zjp[p], NEG1_2, zi[p]);   // z_i - z_j
            unpack2(dz, lo, hi);
            lo = fmaxf(lo, 0.f); hi = fmaxf(hi, 0.f);
            a2[p] = add2(a2[p], pack2(lo, hi));
        }
    }

    // ---- epilogue: self-edge correction, unpack ----
    float af[16], p2v[16];
    #pragma unroll
    for (int p = 0; p < 8; p++) {
        float bl, bh; unpack2(b1p[p], bl, bh);
        float lo, hi;
        unpack2(a1[p], lo, hi);
        af[2 * p + 0] = lo - fmaxf(bl, 0.f);
        af[2 * p + 1] = hi - fmaxf(bh, 0.f);
        unpack2(a2[p], lo, hi);
        p2v[2 * p + 0] = lo;
        p2v[2 * p + 1] = hi;
    }
    float s = 0.f, ssq = 0.f;
    #pragma unroll
    for (int k = 0; k < 16; k++) { s += af[k]; ssq += af[k] * af[k]; }

    __syncthreads();   // j-loop done: ws & zs reusable

    // LN partials: red[i][16] in ws; p2 stage in zs[i*128+d]
    ws[i_l * 16 + dwin * 2 + 0] = s;
    ws[i_l * 16 + dwin * 2 + 1] = ssq;
    {
        float* stg = zs + i_l * 128 + dbase;
        #pragma unroll
        for (int q = 0; q < 4; q++) {
            float4 o;
            o.x = p2v[q * 4 + 0]; o.y = p2v[q * 4 + 1];
            o.z = p2v[q * 4 + 2]; o.w = p2v[q * 4 + 3];
            *(float4*)(stg + q * 4) = o;
        }
    }
    __syncthreads();

    // per-node LN stats (each thread redundantly for its i)
    float S = 0.f, Q = 0.f;
    #pragma unroll
    for (int c = 0; c < 8; c++) {
        S += ws[i_l * 16 + 2 * c + 0];
        Q += ws[i_l * 16 + 2 * c + 1];
    }
    float mu  = S * (1.f / 128.f);
    float inv = 1.f / sqrtf(Q * (1.f / 128.f) - mu * mu + EPSV);

    // BN partials (column reduce p2 stage)
    if (tid < 128) {
        float Sb = 0.f, SSb = 0.f;
        #pragma unroll 8
        for (int i = 0; i < 64; i++) {
            float v = zs[i * 128 + tid];
            Sb += v; SSb += v * v;
        }
        g_ps[cta * 128 + tid]  = Sb;
        g_pss[cta * 128 + tid] = SSb;
    }

    // ---- resident-grid sync: last CTA computes bstats ----
    __shared__ unsigned s_tk;
    __threadfence();
    if (tid == 0) s_tk = atomicAdd(&g_cnt, 1u);
    __syncthreads();
    if (s_tk == 127u) {
        __threadfence();
        const int d   = tid & 127;
        const int grp = tid >> 7;   // 0..3, 32 CTAs each
        const float* ps  = g_ps  + grp * 32 * 128 + d;
        const float* pss = g_pss + grp * 32 * 128 + d;
        float Sg = 0.f, SSg = 0.f;
        #pragma unroll 8
        for (int c = 0; c < 32; c++) {
            Sg  += ps[c * 128];
            SSg += pss[c * 128];
        }
        ws[grp * 128 + d]       = Sg;     // ws free (LN stats already in regs)
        ws[512 + grp * 128 + d] = SSg;
        __syncthreads();
        if (tid < 128) {
            float St  = ws[tid] + ws[128 + tid] + ws[256 + tid] + ws[384 + tid];
            float SSt = ws[512 + tid] + ws[640 + tid] + ws[768 + tid] + ws[896 + tid];
            float bmu  = St * (1.f / (float)NNODES);
            float bvar = SSt * (1.f / (float)NNODES) - bmu * bmu;
            float binv = 1.f / sqrtf(bvar + EPSV);
            float scale = binv * bn_g[tid];
            g_bstats[tid]       = scale;
            g_bstats[128 + tid] = bn_b[tid] - bmu * scale;
        }
        __syncthreads();
        if (tid == 0) {
            __threadfence();
            atomicExch(&g_flag, 1u);
        }
    } else if (tid == 0) {
        while (atomicAdd(&g_flag, 0u) == 0u) __nanosleep(64);
    }
    __syncthreads();
    __threadfence();

    // ---- final write: out = x + LN(p1) + BN(p2) ----
    int gb = ((node0 + i0 + i_l) << 7) + dbase;
    #pragma unroll
    for (int q = 0; q < 4; q++) {
        float4 xv = *(const float4*)(X + gb + q * 4);
        float4 gv = *(const float4*)(ln_g + dbase + q * 4);
        float4 bv = *(const float4*)(ln_b + dbase + q * 4);
        float4 sc = *(const float4*)(g_bstats + dbase + q * 4);
        float4 sh = *(const float4*)(g_bstats + 128 + dbase + q * 4);
        float4 o;
        o.x = xv.x + (af[q * 4 + 0] - mu) * inv * gv.x + bv.x + p2v[q * 4 + 0] * sc.x + sh.x;
        o.y = xv.y + (af[q * 4 + 1] - mu) * inv * gv.y + bv.y + p2v[q * 4 + 1] * sc.y + sh.y;
        o.z = xv.z + (af[q * 4 + 2] - mu) * inv * gv.z + bv.z + p2v[q * 4 + 2] * sc.z + sh.z;
        o.w = xv.w + (af[q * 4 + 3] - mu) * inv * gv.w + bv.w + p2v[q * 4 + 3] * sc.w + sh.w;
        *(float4*)(out + gb + q * 4) = o;
    }

    // ---- reset for next (graph-replayed) launch ----
    if (tid == 0) {
        unsigned t2 = atomicAdd(&g_cnt2, 1u);
        if (t2 == 127u) {
            g_cnt  = 0u;
            g_cnt2 = 0u;
            g_flag = 0u;
        }
    }
}

// ============================================================================
extern "C" void kernel_launch(void* const* d_in, const int* in_sizes, int n_in,
                              void* d_out, int out_size) {
    const float* X    = (const float*)d_in[0];
    const float* XYZ  = (const float*)d_in[1];
    const float* Wxyz = (const float*)d_in[2];
    const float* bn_g = (const float*)d_in[3];
    const float* bn_b = (const float*)d_in[4];
    const float* W1   = (const float*)d_in[5];
    const float* b1   = (const float*)d_in[6];
    const float* ln_g = (const float*)d_in[7];
    const float* ln_b = (const float*)d_in[8];
    float* out = (float*)d_out;

    const int smem0 = (2 * 128 + 2 * 64) * LDB * 2;   // ~102 KB
    const int smemF = SMF_FLOATS * 4;                 // ~163.5 KB

    cudaFuncSetAttribute(k0_gemm, cudaFuncAttributeMaxDynamicSharedMemorySize, smem0);
    cudaFuncSetAttribute(kfused,  cudaFuncAttributeMaxDynamicSharedMemorySize, smemF);

    k0_gemm<<<128, 256, smem0>>>(X, W1);
    kfused <<<128, 512, smemF>>>(X, XYZ, Wxyz, bn_g, bn_b, b1, ln_g, ln_b, out);
}